// round 5
// baseline (speedup 1.0000x reference)
#include <cuda_runtime.h>
#include <cuda_bf16.h>

// Pendulum RK4 trajectory, N=200000, T=100. out[N][T][2] fp32.
// R2: 297us — scalar strided stores, L1tex wavefront bound (issue 9.8%).
// R4: 46.9us — smem-staged warp-transpose float4 stores; now issue-bound
//     (issue 77.9%, ~65 slots/step of scalar FFMA).
// R5: pack (theta, omega) into Blackwell f32x2 packed ops (fma.rn.f32x2) —
//     ~26 slots/step. Sin stays on MUFU (separate pipe, ~18us, hidden).

#define PEND_N 200000
#define PEND_T 100
#define PEND_G 10.0f
#define TC      16          // slots per flush chunk
#define ROWF2   18          // padded row length in float2 (144B)
#define NWARPS  8

typedef unsigned long long u64;

// ---- f32x2 packed helpers (sm_100a; ptxas never auto-emits these) ----
__device__ __forceinline__ u64 pack2(float lo, float hi) {
    u64 r; asm("mov.b64 %0, {%1, %2};" : "=l"(r) : "f"(lo), "f"(hi)); return r;
}
__device__ __forceinline__ float lo2(u64 v) {
    float a, b; asm("mov.b64 {%0, %1}, %2;" : "=f"(a), "=f"(b) : "l"(v)); return a;
}
__device__ __forceinline__ float hi2(u64 v) {
    float a, b; asm("mov.b64 {%0, %1}, %2;" : "=f"(a), "=f"(b) : "l"(v)); return b;
}
__device__ __forceinline__ u64 fma2(u64 a, u64 b, u64 c) {
    u64 d; asm("fma.rn.f32x2 %0, %1, %2, %3;" : "=l"(d) : "l"(a), "l"(b), "l"(c)); return d;
}
__device__ __forceinline__ u64 add2(u64 a, u64 b) {
    u64 d; asm("add.rn.f32x2 %0, %1, %2;" : "=l"(d) : "l"(a), "l"(b)); return d;
}
__device__ __forceinline__ u64 mul2(u64 a, u64 b) {
    u64 d; asm("mul.rn.f32x2 %0, %1, %2;" : "=l"(d) : "l"(a), "l"(b)); return d;
}

__global__ __launch_bounds__(256) void pendulum_rk4_kernel(
    const float* __restrict__ t,
    const float* __restrict__ z0,
    const float* __restrict__ params,
    float* __restrict__ out,
    int n)
{
    __shared__ __align__(8) float2 sdt2[PEND_T - 1];   // {dt, dt} duplicated
    __shared__ __align__(16) float2 buf[NWARPS][32][ROWF2];

    for (int j = threadIdx.x; j < PEND_T - 1; j += blockDim.x) {
        const float d = t[j + 1] - t[j];
        sdt2[j] = make_float2(d, d);
    }
    __syncthreads();

    const int warp = threadIdx.x >> 5;
    const int lane = threadIdx.x & 31;
    const int warpbase = blockIdx.x * blockDim.x + warp * 32;
    if (warpbase >= n) return;            // n multiple of 32: whole warps only

    float2 (* __restrict__ mybuf)[ROWF2] = buf[warp];

    const int i = warpbase + lane;
    const float2 z = reinterpret_cast<const float2*>(z0)[i];
    const float coef = -(PEND_G / params[i]);

    // y = {theta (lo), omega (hi)} as a packed f32x2 register pair.
    u64 y = pack2(z.x, z.y);

    // Hoisted packed constants.
    const u64 C_THIRD  = pack2( 1.0f/3.0f,  1.0f/3.0f);
    const u64 C_NTHIRD = pack2(-1.0f/3.0f, -1.0f/3.0f);
    const u64 C_EIGHTH = pack2( 0.125f,     0.125f);
    const u64 C_THREE  = pack2( 3.0f,       3.0f);
    const u64 C_NEG1   = pack2(-1.0f,      -1.0f);

    float4* __restrict__ out4 = reinterpret_cast<float4*>(out);
    const size_t rowbase = (size_t)warpbase * (PEND_T / 2);

    const u64* __restrict__ sdtq = reinterpret_cast<const u64*>(sdt2);

    int base = 0;
    #pragma unroll 1
    for (int c = 0; c < 7; c++) {
        const int cnt = (c < 6) ? TC : (PEND_T - 6 * TC);   // 16 x6, then 4

        #pragma unroll 1
        for (int k = 0; k < cnt; k++) {
            const int g = base + k;                // uniform across warp
            if (g > 0) {
                const u64 dt2 = sdtq[g - 1];       // LDS.64 of {dt,dt}
                const u64 dt3 = mul2(dt2, C_THIRD);
                const u64 dt8 = mul2(dt2, C_EIGHTH);

                // stage(y_s): k = { omega_s, coef*sin(theta_s) }
                const u64 k1 = pack2(hi2(y),  coef * __sinf(lo2(y)));
                const u64 y2 = fma2(k1, dt3, y);
                const u64 k2 = pack2(hi2(y2), coef * __sinf(lo2(y2)));
                u64 tmp      = fma2(k1, C_NTHIRD, k2);      // k2 - k1/3
                const u64 y3 = fma2(tmp, dt2, y);
                const u64 k3 = pack2(hi2(y3), coef * __sinf(lo2(y3)));
                tmp          = fma2(k2, C_NEG1, k1);        // k1 - k2
                tmp          = add2(tmp, k3);               // + k3
                const u64 y4 = fma2(tmp, dt2, y);
                const u64 k4 = pack2(hi2(y4), coef * __sinf(lo2(y4)));
                u64 s        = add2(k2, k3);
                s            = fma2(s, C_THREE, k1);        // k1 + 3(k2+k3)
                s            = add2(s, k4);                 // + k4
                y            = fma2(s, dt8, y);             // y += dt/8 * s
            }
            *reinterpret_cast<u64*>(&mybuf[lane][k]) = y;   // STS.64
        }
        __syncwarp();

        // ---- flush: warp transpose, coalesced float4 stores ----
        const int f4pp = cnt >> 1;                 // float4 per particle (8 or 2)
        #pragma unroll
        for (int j = 0; j < TC / 2; j++) {
            if (j >= f4pp) break;
            const int idx = j * 32 + lane;
            const int p   = idx / f4pp;
            const int s4  = idx - p * f4pp;
            const float4 v = *reinterpret_cast<const float4*>(&mybuf[p][s4 * 2]);
            out4[rowbase + (size_t)p * (PEND_T / 2) + (base >> 1) + s4] = v;
        }
        __syncwarp();

        base += cnt;
    }
}

extern "C" void kernel_launch(void* const* d_in, const int* in_sizes, int n_in,
                              void* d_out, int out_size)
{
    (void)n_in; (void)out_size;
    const float* t      = (const float*)d_in[1];
    const float* z0     = (const float*)d_in[2];
    const float* params = (const float*)d_in[3];
    float* out          = (float*)d_out;

    const int n = in_sizes[3];
    const int threads = 256;
    const int blocks  = (n + threads - 1) / threads;
    pendulum_rk4_kernel<<<blocks, threads>>>(t, z0, params, out, n);
}

// round 8
// speedup vs baseline: 1.2567x; 1.2567x over previous
#include <cuda_runtime.h>
#include <cuda_bf16.h>

// Pendulum RK4 trajectory, N=200000, T=100. out[N][T][2] fp32.
// R2: 297us  scalar strided stores (L1tex wavefront bound, issue 9.8%)
// R4: 46.9us smem-staged warp-transpose float4 stores (issue-bound, 77.9%)
// R5: 49.2us f32x2 packing FAILED (pack/unpack MOVs ate the savings)
// R6-R8: scalar, fully-unrolled 16-step chunks, LDS.128 {dt,dt/3,dt/8}
//     triples, special-cased first/last chunk (no per-step predicate).

#define PEND_T 100
#define PEND_G 10.0f
#define ROWF2  18           // padded particle row in float2 (144B = 9*16B)
#define NWARPS 8

__device__ __forceinline__ void rk4_step(float& theta, float& omega,
                                         float coef, float4 d)
{
    const float dt = d.x, dt3 = d.y, dt8 = d.z;
    const float third = 1.0f / 3.0f;

    const float k1t = omega;
    const float k1w = coef * __sinf(theta);

    const float y2t = fmaf(dt3, k1t, theta);
    const float y2w = fmaf(dt3, k1w, omega);
    const float k2t = y2w;
    const float k2w = coef * __sinf(y2t);

    const float e3t = fmaf(-third, k1t, k2t);      // k2 - k1/3
    const float e3w = fmaf(-third, k1w, k2w);
    const float y3t = fmaf(dt, e3t, theta);
    const float y3w = fmaf(dt, e3w, omega);
    const float k3t = y3w;
    const float k3w = coef * __sinf(y3t);

    const float e4t = (k1t - k2t) + k3t;           // k1 - k2 + k3
    const float e4w = (k1w - k2w) + k3w;
    const float y4t = fmaf(dt, e4t, theta);
    const float y4w = fmaf(dt, e4w, omega);
    const float k4t = y4w;
    const float k4w = coef * __sinf(y4t);

    const float st = fmaf(3.0f, k2t + k3t, k1t) + k4t;   // k1+3(k2+k3)+k4
    const float sw = fmaf(3.0f, k2w + k3w, k1w) + k4w;
    theta = fmaf(dt8, st, theta);
    omega = fmaf(dt8, sw, omega);
}

// Flush one 16-slot chunk: 8 float4 per particle, 8 lanes per particle,
// fully coalesced STG.128 covering whole 128B lines.
__device__ __forceinline__ void flush16(const float2 (* __restrict__ mybuf)[ROWF2],
                                        float4* __restrict__ out4,
                                        size_t rowbase, int lane, int base)
{
    __syncwarp();
    #pragma unroll
    for (int j = 0; j < 8; j++) {
        const int idx = j * 32 + lane;
        const int p   = idx >> 3;          // particle within warp
        const int s4  = idx & 7;           // float4 slot within chunk
        const float4 v = *reinterpret_cast<const float4*>(&mybuf[p][s4 * 2]);
        out4[rowbase + (size_t)p * (PEND_T / 2) + (base >> 1) + s4] = v;
    }
    __syncwarp();
}

__global__ __launch_bounds__(256) void pendulum_rk4_kernel(
    const float* __restrict__ t,
    const float* __restrict__ z0,
    const float* __restrict__ params,
    float* __restrict__ out,
    int n)
{
    __shared__ __align__(16) float4 sdt4[PEND_T - 1];   // {dt, dt/3, dt/8, -}
    __shared__ __align__(16) float2 buf[NWARPS][32][ROWF2];

    for (int j = threadIdx.x; j < PEND_T - 1; j += blockDim.x) {
        const float d = t[j + 1] - t[j];
        sdt4[j] = make_float4(d, d * (1.0f / 3.0f), d * 0.125f, 0.0f);
    }
    __syncthreads();

    const int warp = threadIdx.x >> 5;
    const int lane = threadIdx.x & 31;
    const int warpbase = blockIdx.x * blockDim.x + warp * 32;
    if (warpbase >= n) return;            // n multiple of 32: whole warps only

    float2 (* __restrict__ mybuf)[ROWF2] = buf[warp];

    const int i = warpbase + lane;
    const float2 z = reinterpret_cast<const float2*>(z0)[i];
    float theta = z.x;
    float omega = z.y;
    const float coef = -(PEND_G / params[i]);

    float4* __restrict__ out4 = reinterpret_cast<float4*>(out);
    const size_t rowbase = (size_t)warpbase * (PEND_T / 2);   // 50 float4/row

    // ---- chunk 0: slot 0 (initial state) + steps 1..15 ----
    mybuf[lane][0] = make_float2(theta, omega);
    #pragma unroll
    for (int k = 1; k < 16; k++) {
        rk4_step(theta, omega, coef, sdt4[k - 1]);
        mybuf[lane][k] = make_float2(theta, omega);
    }
    flush16(mybuf, out4, rowbase, lane, 0);

    // ---- chunks 1..5: 16 steps each (outer loop rolled for I-cache) ----
    #pragma unroll 1
    for (int c = 1; c < 6; c++) {
        const int base = c * 16;
        #pragma unroll
        for (int k = 0; k < 16; k++) {
            rk4_step(theta, omega, coef, sdt4[base - 1 + k]);
            mybuf[lane][k] = make_float2(theta, omega);
        }
        flush16(mybuf, out4, rowbase, lane, base);
    }

    // ---- tail: steps 96..99 (4 slots = 2 float4 per particle) ----
    #pragma unroll
    for (int k = 0; k < 4; k++) {
        rk4_step(theta, omega, coef, sdt4[95 + k]);
        mybuf[lane][k] = make_float2(theta, omega);
    }
    __syncwarp();
    #pragma unroll
    for (int j = 0; j < 2; j++) {
        const int idx = j * 32 + lane;
        const int p   = idx >> 1;
        const int s4  = idx & 1;
        const float4 v = *reinterpret_cast<const float4*>(&mybuf[p][s4 * 2]);
        out4[rowbase + (size_t)p * (PEND_T / 2) + 48 + s4] = v;
    }
}

extern "C" void kernel_launch(void* const* d_in, const int* in_sizes, int n_in,
                              void* d_out, int out_size)
{
    (void)n_in; (void)out_size;
    // d_in[0] = mini_batch (unused), d_in[1] = t, d_in[2] = z0, d_in[3] = params
    const float* t      = (const float*)d_in[1];
    const float* z0     = (const float*)d_in[2];
    const float* params = (const float*)d_in[3];
    float* out          = (float*)d_out;

    const int n = in_sizes[3];
    const int threads = 256;
    const int blocks  = (n + threads - 1) / threads;
    pendulum_rk4_kernel<<<blocks, threads>>>(t, z0, params, out, n);
}